// round 17
// baseline (speedup 1.0000x reference)
#include <cuda_runtime.h>
#include <cuda_fp16.h>
#include <cstdint>

// ============================================================================
// y = x @ W_eff^T + b_eff   (exact collapse of the one-hot op mixture)
// x: [131072, 128] fp32.  Single fp16 product (rel_err ~2.9e-4).
// R17: warp tile 32x128 (TILE_M=256).  Each warp owns 32 rows as two 16-row
//   subtiles sharing ONE set of B ldmatrix fragments per k-step -> B
//   wavefronts per 128 rows halve (2048 -> 1024); total L1 wf floor
//   4096 -> 3072 per 128 rows.  R16 pipelining reverted (measured neutral);
//   bias moved to SMEM epilogue loads to fund the 128 fp32 accumulators.
//   R15's k-perm + n-perm W staging and STG.128 epilogue retained.
// ============================================================================

static constexpr int D       = 128;
static constexpr int TILE_M  = 256;
static constexpr int N_TILES = 512;                  // 131072 / 256
static constexpr int GRID    = 148;                  // persistent, 1 CTA/SM
static constexpr int NTHR    = 256;                  // 8 warps x 32 rows

static constexpr int PITCHW  = 272;                  // fp16 W tile pitch
static constexpr int WTILE   = 128 * PITCHW;         // 34816 B
static constexpr int SM_W    = 0;
static constexpr int SM_BIAS = WTILE;                // 512 B
static constexpr int SM_TOTAL = WTILE + 512;

// ---------------- PTX helpers (baseline ISA only) ---------------------------

__device__ __forceinline__ uint32_t smem_to_u32(const void* p) {
    uint32_t a;
    asm("{ .reg .u64 t; cvta.to.shared.u64 t, %1; cvt.u32.u64 %0, t; }"
        : "=r"(a) : "l"(p));
    return a;
}

__device__ __forceinline__ void ldmatrix_x4(uint32_t& r0, uint32_t& r1,
                                            uint32_t& r2, uint32_t& r3,
                                            uint32_t addr) {
    asm volatile("ldmatrix.sync.aligned.m8n8.x4.shared.b16 {%0,%1,%2,%3}, [%4];"
                 : "=r"(r0), "=r"(r1), "=r"(r2), "=r"(r3) : "r"(addr));
}

__device__ __forceinline__ void mma_f16(float* c, const uint32_t* a,
                                        const uint32_t* b) {
    asm volatile(
        "mma.sync.aligned.m16n8k16.row.col.f32.f16.f16.f32 "
        "{%0,%1,%2,%3}, {%4,%5,%6,%7}, {%8,%9}, {%0,%1,%2,%3};"
        : "+f"(c[0]), "+f"(c[1]), "+f"(c[2]), "+f"(c[3])
        : "r"(a[0]), "r"(a[1]), "r"(a[2]), "r"(a[3]), "r"(b[0]), "r"(b[1]));
}

__device__ __forceinline__ uint32_t pack_h2(float a, float b) {
    __half2 h = __floats2half2_rn(a, b);
    return *(uint32_t*)&h;
}

// ============================================================================
__global__ void __launch_bounds__(NTHR, 1)
gemm_kernel(const float* __restrict__ x,
            const float* __restrict__ W,
            const float* __restrict__ bias,
            const float* __restrict__ wsel,
            float* __restrict__ y) {
    extern __shared__ char smem[];
    const uint32_t sb  = smem_to_u32(smem);
    const int tid  = threadIdx.x;
    const int w    = tid >> 5;       // warp 0..7 -> rows w*32 .. w*32+31
    const int l    = tid & 31;

    const float w0 = wsel[0], w1 = wsel[1], w2 = wsel[2], w3 = wsel[3];

    // ---- stage W_eff (fp16) into SMEM with BOTH permutations ----
    // col (k-perm): fragment-k (2j+m)<-data-k(4j+m); (2j+8+m)<-(4j+2+m).
    // row (n-perm): f = 16k+4m+u -> npos = 16k + (u<2 ? 2m+u : 8+2m+(u-2)).
#pragma unroll
    for (int jj = 0; jj < 64; jj++) {                // 16384 / 256
        const int idx = tid + jj * NTHR;
        const float v = w0 * W[idx] + w1 * W[16384 + idx]
                      + w2 * W[32768 + idx] + w3 * W[49152 + idx];
        const int f  = idx >> 7, d = idx & 127;
        const int bblk = d >> 4, dk = d & 15;
        const int j  = dk >> 2, m = dk & 3;
        const int fk = 2 * j + m + ((m >= 2) ? 6 : 0);
        const int col = bblk * 16 + fk;
        const int k = f >> 4, r = f & 15;
        const int q = r >> 2, u = r & 3;
        const int npos = 16 * k + ((u < 2) ? (2 * q + u) : (8 + 2 * q + (u - 2)));
        *(__half*)(smem + SM_W + npos * PITCHW + col * 2) = __float2half_rn(v);
    }
    if (tid < 128) {
        ((float*)(smem + SM_BIAS))[tid] =
            w0 * bias[tid] + w1 * bias[128 + tid]
          + w2 * bias[256 + tid] + w3 * bias[384 + tid];
    }
    __syncthreads();                 // the ONLY block-wide barrier

    // B ldmatrix per-lane offset (both permutations handled in staging)
    const uint32_t boff = (uint32_t)((((l >> 4) & 1) * 8 + (l & 7)) * PITCHW
                                     + ((l >> 3) & 1) * 16);
    const uint32_t sW = sb + SM_W;

    // per-thread A row/col: subtile mt rows = t*256 + w*32 + mt*16 + l/4
    const int rbase_in_tile = w * 32 + (l >> 2);
    const int acol = (l & 3) * 4;
    const int m4   = (l & 3) * 4;
    const float* bsm = (const float*)(smem + SM_BIAS);

    for (int t = blockIdx.x; t < N_TILES; t += GRID) {
        const float* xr = x + ((size_t)t * TILE_M + rbase_in_tile) * D + acol;

        float acc[2][16][4];
#pragma unroll
        for (int mt = 0; mt < 2; mt++)
#pragma unroll
            for (int nt = 0; nt < 16; nt++)
#pragma unroll
                for (int j = 0; j < 4; j++) acc[mt][nt][j] = 0.0f;

#pragma unroll
        for (int ks = 0; ks < 8; ks++) {
            // A fragments for BOTH 16-row subtiles (k-permuted mapping)
            const float4 lo0 = *(const float4*)(xr + ks * 16);            // r
            const float4 hi0 = *(const float4*)(xr + 8 * D + ks * 16);    // r+8
            const float4 lo1 = *(const float4*)(xr + 16 * D + ks * 16);   // r+16
            const float4 hi1 = *(const float4*)(xr + 24 * D + ks * 16);   // r+24
            uint32_t a0[4], a1[4];
            a0[0] = pack_h2(lo0.x, lo0.y);
            a0[1] = pack_h2(hi0.x, hi0.y);
            a0[2] = pack_h2(lo0.z, lo0.w);
            a0[3] = pack_h2(hi0.z, hi0.w);
            a1[0] = pack_h2(lo1.x, lo1.y);
            a1[1] = pack_h2(hi1.x, hi1.y);
            a1[2] = pack_h2(lo1.z, lo1.w);
            a1[3] = pack_h2(hi1.z, hi1.w);

            // B fragments ONCE, shared by both subtiles
            uint32_t bq[8][4];
#pragma unroll
            for (int np = 0; np < 8; np++) {
                const uint32_t nb = (uint32_t)(np * 16) * PITCHW;
                ldmatrix_x4(bq[np][0], bq[np][1], bq[np][2], bq[np][3],
                            sW + boff + nb + (uint32_t)ks * 32);
            }

            // 32 MMAs
#pragma unroll
            for (int np = 0; np < 8; np++) {
                mma_f16(acc[0][np * 2 + 0], a0, &bq[np][0]);
                mma_f16(acc[0][np * 2 + 1], a0, &bq[np][2]);
                mma_f16(acc[1][np * 2 + 0], a1, &bq[np][0]);
                mma_f16(acc[1][np * 2 + 1], a1, &bq[np][2]);
            }
        }

        // epilogue: per subtile, n-tile pair (2k,2k+1) covers cols 16k+4m..+3
#pragma unroll
        for (int mt = 0; mt < 2; mt++) {
            const size_t row = (size_t)t * TILE_M + rbase_in_tile + mt * 16;
            float* y0 = y + row * D + m4;
            float* y1 = y + (row + 8) * D + m4;
#pragma unroll
            for (int k = 0; k < 8; k++) {
                const float4 bk = *(const float4*)(bsm + 16 * k + m4);
                float4 v0, v1;
                v0.x = acc[mt][2 * k][0]     + bk.x;
                v0.y = acc[mt][2 * k][1]     + bk.y;
                v0.z = acc[mt][2 * k + 1][0] + bk.z;
                v0.w = acc[mt][2 * k + 1][1] + bk.w;
                v1.x = acc[mt][2 * k][2]     + bk.x;
                v1.y = acc[mt][2 * k][3]     + bk.y;
                v1.z = acc[mt][2 * k + 1][2] + bk.z;
                v1.w = acc[mt][2 * k + 1][3] + bk.w;
                *(float4*)(y0 + 16 * k) = v0;
                *(float4*)(y1 + 16 * k) = v1;
            }
        }
    }
}

// ============================================================================

extern "C" void kernel_launch(void* const* d_in, const int* in_sizes, int n_in,
                              void* d_out, int out_size) {
    const float* x    = (const float*)d_in[0];  // [16, 8192, 128]
    const float* W    = (const float*)d_in[1];  // [4, 128, 128]
    const float* b    = (const float*)d_in[2];  // [4, 128]
    const float* wsel = (const float*)d_in[3];  // [4]
    float* y = (float*)d_out;                   // [16, 8192, 128]

    static bool attr_set = false;
    if (!attr_set) {
        cudaFuncSetAttribute(gemm_kernel,
                             cudaFuncAttributeMaxDynamicSharedMemorySize, SM_TOTAL);
        attr_set = true;
    }
    gemm_kernel<<<GRID, NTHR, SM_TOTAL>>>(x, W, b, wsel, y);
}